// round 1
// baseline (speedup 1.0000x reference)
#include <cuda_runtime.h>
#include <cstdint>

// Problem dims
#define BATCH 65536
#define DIN   784
#define DH    320
#define DOUT  10
#define THRESH 0.001f

// Intermediate ternarized hidden activations, int8 {-1,0,1}
__device__ __align__(16) int8_t g_h[(size_t)BATCH * DH];

__device__ __forceinline__ int tern_i(float v) {
    return v > THRESH ? 1 : (v < -THRESH ? -1 : 0);
}

// ---- packed f32x2 helpers (sm_103a) ----
__device__ __forceinline__ unsigned long long dup2(float v) {
    unsigned long long r;
    asm("mov.b64 %0, {%1, %1};" : "=l"(r) : "f"(v));
    return r;
}
__device__ __forceinline__ void ffma2(unsigned long long& d,
                                      unsigned long long a,
                                      unsigned long long b) {
    asm("fma.rn.f32x2 %0, %1, %2, %0;" : "+l"(d) : "l"(a), "l"(b));
}
__device__ __forceinline__ float2 unpk2(unsigned long long v) {
    float2 r;
    asm("mov.b64 {%0, %1}, %2;" : "=f"(r.x), "=f"(r.y) : "l"(v));
    return r;
}

// ============================================================================
// Kernel 1: h = ternarize( x @ tern(w1)^T + b1 )  → int8 g_h
// GEMM: M=65536, N=320, K=784. Tile: BM=128, BN=64, BK=16. 256 threads.
// Each thread: 8 rows x 4 cols = 32 fp32 accumulators as 16 f32x2.
// Double-buffered SMEM, LDG for next tile overlapped with compute.
// ============================================================================
constexpr int BM = 128, BN = 64, BK = 16;
constexpr int XS_LD = BM + 4;  // 132 floats/row (pad)
constexpr int WS_LD = BN + 4;  // 68

__global__ __launch_bounds__(256, 2)
void gemm1_kernel(const float* __restrict__ x,
                  const float* __restrict__ w1,
                  const float* __restrict__ b1) {
    __shared__ float xs[2][BK][XS_LD];
    __shared__ float ws[2][BK][WS_LD];

    const int tid = threadIdx.x;
    const int tx  = tid & 15;   // N direction (16 * 4 = 64)
    const int ty  = tid >> 4;   // M direction (16 * 8 = 128)

    // grid: x = N tiles (5), y = M tiles (512) so all 5 N-tiles of an M-tile
    // are co-resident → x tile reuse through L2.
    const int n0 = blockIdx.x * BN;
    const int m0 = blockIdx.y * BM;

    // global-load assignments
    const int xrow = tid >> 2;          // 0..63 (and +64 for second half)
    const int xkq  = (tid & 3) * 4;     // k offset within 16
    const int wrow = tid >> 2;          // 0..63
    const int wkq  = (tid & 3) * 4;

    unsigned long long acc[4][4];
#pragma unroll
    for (int i = 0; i < 4; i++)
#pragma unroll
        for (int j = 0; j < 4; j++) acc[i][j] = 0ull;

    float4 xa, xb, wa;

    // ---- prologue: load k-tile 0 ----
    {
        xa = *(const float4*)(x + (size_t)(m0 + xrow) * DIN + xkq);
        xb = *(const float4*)(x + (size_t)(m0 + xrow + 64) * DIN + xkq);
        float4 wt = *(const float4*)(w1 + (size_t)(n0 + wrow) * DIN + wkq);
        wa.x = (float)tern_i(wt.x); wa.y = (float)tern_i(wt.y);
        wa.z = (float)tern_i(wt.z); wa.w = (float)tern_i(wt.w);

        xs[0][xkq + 0][xrow] = xa.x; xs[0][xkq + 1][xrow] = xa.y;
        xs[0][xkq + 2][xrow] = xa.z; xs[0][xkq + 3][xrow] = xa.w;
        xs[0][xkq + 0][xrow + 64] = xb.x; xs[0][xkq + 1][xrow + 64] = xb.y;
        xs[0][xkq + 2][xrow + 64] = xb.z; xs[0][xkq + 3][xrow + 64] = xb.w;
        ws[0][wkq + 0][wrow] = wa.x; ws[0][wkq + 1][wrow] = wa.y;
        ws[0][wkq + 2][wrow] = wa.z; ws[0][wkq + 3][wrow] = wa.w;
    }
    __syncthreads();

    const int NKT = DIN / BK;  // 49
    for (int kt = 0; kt < NKT; kt++) {
        const int s = kt & 1;

        // issue next tile's global loads early (hide LDG latency under compute)
        if (kt + 1 < NKT) {
            const int k0 = (kt + 1) * BK;
            xa = *(const float4*)(x + (size_t)(m0 + xrow) * DIN + k0 + xkq);
            xb = *(const float4*)(x + (size_t)(m0 + xrow + 64) * DIN + k0 + xkq);
            float4 wt = *(const float4*)(w1 + (size_t)(n0 + wrow) * DIN + k0 + wkq);
            wa.x = (float)tern_i(wt.x); wa.y = (float)tern_i(wt.y);
            wa.z = (float)tern_i(wt.z); wa.w = (float)tern_i(wt.w);
        }

        // ---- compute on stage s ----
#pragma unroll
        for (int k = 0; k < BK; k++) {
            const ulonglong2* xp =
                (const ulonglong2*)&xs[s][k][ty * 8];
            ulonglong2 p0 = xp[0];  // rows (0,1),(2,3)
            ulonglong2 p1 = xp[1];  // rows (4,5),(6,7)
            float4 wv = *(const float4*)&ws[s][k][tx * 4];
            unsigned long long wd0 = dup2(wv.x);
            unsigned long long wd1 = dup2(wv.y);
            unsigned long long wd2 = dup2(wv.z);
            unsigned long long wd3 = dup2(wv.w);

            ffma2(acc[0][0], p0.x, wd0); ffma2(acc[0][1], p0.x, wd1);
            ffma2(acc[0][2], p0.x, wd2); ffma2(acc[0][3], p0.x, wd3);
            ffma2(acc[1][0], p0.y, wd0); ffma2(acc[1][1], p0.y, wd1);
            ffma2(acc[1][2], p0.y, wd2); ffma2(acc[1][3], p0.y, wd3);
            ffma2(acc[2][0], p1.x, wd0); ffma2(acc[2][1], p1.x, wd1);
            ffma2(acc[2][2], p1.x, wd2); ffma2(acc[2][3], p1.x, wd3);
            ffma2(acc[3][0], p1.y, wd0); ffma2(acc[3][1], p1.y, wd1);
            ffma2(acc[3][2], p1.y, wd2); ffma2(acc[3][3], p1.y, wd3);
        }

        // ---- store next tile into other stage ----
        if (kt + 1 < NKT) {
            const int sn = s ^ 1;
            xs[sn][xkq + 0][xrow] = xa.x; xs[sn][xkq + 1][xrow] = xa.y;
            xs[sn][xkq + 2][xrow] = xa.z; xs[sn][xkq + 3][xrow] = xa.w;
            xs[sn][xkq + 0][xrow + 64] = xb.x; xs[sn][xkq + 1][xrow + 64] = xb.y;
            xs[sn][xkq + 2][xrow + 64] = xb.z; xs[sn][xkq + 3][xrow + 64] = xb.w;
            ws[sn][wkq + 0][wrow] = wa.x; ws[sn][wkq + 1][wrow] = wa.y;
            ws[sn][wkq + 2][wrow] = wa.z; ws[sn][wkq + 3][wrow] = wa.w;
        }
        __syncthreads();
    }

    // ---- epilogue: +b1, ternarize, store int8 ----
    float bv0 = b1[n0 + tx * 4 + 0];
    float bv1 = b1[n0 + tx * 4 + 1];
    float bv2 = b1[n0 + tx * 4 + 2];
    float bv3 = b1[n0 + tx * 4 + 3];

    float hb[8][4];
#pragma unroll
    for (int i = 0; i < 4; i++) {
        float2 v0 = unpk2(acc[i][0]);
        float2 v1 = unpk2(acc[i][1]);
        float2 v2 = unpk2(acc[i][2]);
        float2 v3 = unpk2(acc[i][3]);
        hb[2 * i + 0][0] = v0.x + bv0; hb[2 * i + 1][0] = v0.y + bv0;
        hb[2 * i + 0][1] = v1.x + bv1; hb[2 * i + 1][1] = v1.y + bv1;
        hb[2 * i + 0][2] = v2.x + bv2; hb[2 * i + 1][2] = v2.y + bv2;
        hb[2 * i + 0][3] = v3.x + bv3; hb[2 * i + 1][3] = v3.y + bv3;
    }
#pragma unroll
    for (int r = 0; r < 8; r++) {
        char4 c;
        c.x = (signed char)tern_i(hb[r][0]);
        c.y = (signed char)tern_i(hb[r][1]);
        c.z = (signed char)tern_i(hb[r][2]);
        c.w = (signed char)tern_i(hb[r][3]);
        *(char4*)(g_h + (size_t)(m0 + ty * 8 + r) * DH + n0 + tx * 4) = c;
    }
}

// ============================================================================
// Kernel 2: logits = g_h @ tern(w2)^T + b2 ; out = log_softmax(logits)
// One thread per batch row. Exact integer dp4a over ternary operands.
// ============================================================================
__global__ __launch_bounds__(256)
void head_kernel(const float* __restrict__ w2,
                 const float* __restrict__ b2,
                 float* __restrict__ out) {
    __shared__ int   q2p[DOUT][DH / 4];  // packed int8 ternary weights
    __shared__ float b2s[DOUT];

    const int tid = threadIdx.x;
    for (int i = tid; i < DOUT * (DH / 4); i += 256) {
        const int o = i / (DH / 4);
        const int w = i % (DH / 4);
        int word = 0;
#pragma unroll
        for (int j = 0; j < 4; j++) {
            int t = tern_i(w2[o * DH + w * 4 + j]);
            word |= (t & 0xFF) << (8 * j);
        }
        q2p[o][w] = word;
    }
    if (tid < DOUT) b2s[tid] = b2[tid];
    __syncthreads();

    const size_t row = (size_t)blockIdx.x * 256 + tid;
    const uint4* hp = (const uint4*)(g_h + row * DH);

    int acc[DOUT];
#pragma unroll
    for (int o = 0; o < DOUT; o++) acc[o] = 0;

#pragma unroll
    for (int c = 0; c < DH / 16; c++) {  // 20 x uint4 = 320 int8
        uint4 v = hp[c];
        const int w = c * 4;
#pragma unroll
        for (int o = 0; o < DOUT; o++) {
            acc[o] = __dp4a((int)v.x, q2p[o][w + 0], acc[o]);
            acc[o] = __dp4a((int)v.y, q2p[o][w + 1], acc[o]);
            acc[o] = __dp4a((int)v.z, q2p[o][w + 2], acc[o]);
            acc[o] = __dp4a((int)v.w, q2p[o][w + 3], acc[o]);
        }
    }

    float lg[DOUT];
    float m = -1e30f;
#pragma unroll
    for (int o = 0; o < DOUT; o++) {
        lg[o] = (float)acc[o] + b2s[o];
        m = fmaxf(m, lg[o]);
    }
    float s = 0.0f;
#pragma unroll
    for (int o = 0; o < DOUT; o++) s += expf(lg[o] - m);
    const float lse = m + logf(s);

    float* op = out + row * DOUT;
#pragma unroll
    for (int o = 0; o < DOUT; o++) op[o] = lg[o] - lse;
}

// ============================================================================
extern "C" void kernel_launch(void* const* d_in, const int* in_sizes, int n_in,
                              void* d_out, int out_size) {
    const float* x  = (const float*)d_in[0];
    const float* w1 = (const float*)d_in[1];
    const float* b1 = (const float*)d_in[2];
    const float* w2 = (const float*)d_in[3];
    const float* b2 = (const float*)d_in[4];
    float* out = (float*)d_out;

    dim3 g1(DH / BN, BATCH / BM);   // (5, 512)
    gemm1_kernel<<<g1, 256>>>(x, w1, b1);

    head_kernel<<<BATCH / 256, 256>>>(w2, b2, out);
}

// round 3
// speedup vs baseline: 1.9498x; 1.9498x over previous
#include <cuda_runtime.h>
#include <cuda_fp16.h>
#include <cstdint>

#define BATCH 65536
#define DIN   784
#define DH    320
#define DOUT  10
#define THRESH 0.001f

// GEMM1 tiling
#define BM 128
#define BN 80
#define NSTAGE 49          // 49 x 16 fp32 K
#define ASTRIDE 64         // bytes per A smem row (32 halves, XOR-swizzled chunks)
#define BSTRIDE 48         // bytes per B smem row (16 halves + pad to 24)

__device__ __align__(16) int8_t g_h[(size_t)BATCH * DH];
__device__ __align__(16) __half g_w1h[(size_t)DH * DIN];   // ternarized w1, fp16

__device__ __forceinline__ int tern_i(float v) {
    return v > THRESH ? 1 : (v < -THRESH ? -1 : 0);
}
__device__ __forceinline__ uint32_t h2u(__half2 h) {
    return *reinterpret_cast<uint32_t*>(&h);
}

__device__ __forceinline__ void mma16816(float* c, uint32_t a0, uint32_t a1,
                                         uint32_t a2, uint32_t a3,
                                         uint32_t b0, uint32_t b1) {
    asm volatile(
        "mma.sync.aligned.m16n8k16.row.col.f32.f16.f16.f32 "
        "{%0,%1,%2,%3}, {%4,%5,%6,%7}, {%8,%9}, {%0,%1,%2,%3};"
        : "+f"(c[0]), "+f"(c[1]), "+f"(c[2]), "+f"(c[3])
        : "r"(a0), "r"(a1), "r"(a2), "r"(a3), "r"(b0), "r"(b1));
}

// ============================================================================
// prep: ternarize w1 -> fp16 (exact)
// ============================================================================
__global__ void prep_w1(const float* __restrict__ w1) {
    int i = blockIdx.x * 256 + threadIdx.x;
    if (i >= DH * DIN / 2) return;
    float a = w1[2 * i], b = w1[2 * i + 1];
    float ta = (float)tern_i(a), tb = (float)tern_i(b);
    reinterpret_cast<__half2*>(g_w1h)[i] = __floats2half2_rn(ta, tb);
}

// ============================================================================
// GEMM1: h = tern( x @ tern(w1)^T + b1 ), HMMA fp16 2-plane exact split.
// CTA 128x80, 4 warps (each 32M x 80N), K chunks of 16 fp32 -> 32 halves.
// A smem layout: row r (0..127), 4 chunks of 16B: chunk kc at byte
//   r*64 + ((kc ^ ((r>>1)&3)) << 4).   kc0,1 = hi(k0-7, k8-15); kc2,3 = lo.
// B smem: row n (0..79) stride 48B, halves k0..15 at n*48 + k*2.
// ============================================================================
__global__ __launch_bounds__(128)
void gemm1_hmma(const float* __restrict__ x, const float* __restrict__ b1) {
    __shared__ __align__(16) uint8_t As[2][BM * ASTRIDE];  // 2 x 8192
    __shared__ __align__(16) uint8_t Bs[2][BN * BSTRIDE];  // 2 x 3840
    __shared__ float b1s[BN];

    const int tid  = threadIdx.x;
    const int wid  = tid >> 5;
    const int lane = tid & 31;
    const int g    = lane >> 2;      // 0..7
    const int tg   = lane & 3;       // 0..3
    const int m0   = blockIdx.y * BM;
    const int n0   = blockIdx.x * BN;

    if (tid < BN) b1s[tid] = b1[n0 + tid];

    float acc[2][10][4];
#pragma unroll
    for (int mi = 0; mi < 2; mi++)
#pragma unroll
        for (int ni = 0; ni < 10; ni++)
#pragma unroll
            for (int e = 0; e < 4; e++) acc[mi][ni][e] = 0.0f;

    // staging registers
    const int ar = tid >> 2;   // A row within 32-row group
    const int aq = tid & 3;    // which float4 of the 16-fp32 chunk
    float4 ast[4];
    uint4  bst[2];

    // ---- load stage k0 into regs ----
    auto LOADG = [&](int k0) {
#pragma unroll
        for (int i = 0; i < 4; i++)
            ast[i] = *(const float4*)(x + (size_t)(m0 + i * 32 + ar) * DIN + k0 + aq * 4);
#pragma unroll
        for (int i = 0; i < 2; i++) {
            int idx = tid + i * 128;
            if (idx < 160) {
                int rb = idx >> 1, hb = idx & 1;
                bst[i] = *(const uint4*)(g_w1h + (size_t)(n0 + rb) * DIN + k0 + hb * 8);
            }
        }
    };

    // ---- convert + store staged regs into smem buffer ----
    auto STORE = [&](int buf) {
        uint8_t* a = As[buf];
#pragma unroll
        for (int i = 0; i < 4; i++) {
            float4 v = ast[i];
            __half2 hh0 = __floats2half2_rn(v.x, v.y);
            __half2 hh1 = __floats2half2_rn(v.z, v.w);
            float2 f0 = __half22float2(hh0), f1 = __half22float2(hh1);
            uint32_t h0 = h2u(hh0), h1 = h2u(hh1);
            uint32_t l0 = h2u(__floats2half2_rn(v.x - f0.x, v.y - f0.y));
            uint32_t l1 = h2u(__floats2half2_rn(v.z - f1.x, v.w - f1.y));
            // exchange with partner thread (tid^1) to assemble full 16B chunks
            uint32_t ph0 = __shfl_xor_sync(0xFFFFFFFFu, h0, 1);
            uint32_t ph1 = __shfl_xor_sync(0xFFFFFFFFu, h1, 1);
            uint32_t pl0 = __shfl_xor_sync(0xFFFFFFFFu, l0, 1);
            uint32_t pl1 = __shfl_xor_sync(0xFFFFFFFFu, l1, 1);
            const int r  = i * 32 + ar;
            const int vx = (r >> 1) & 3;
            if ((aq & 1) == 0) {
                const int kc = aq >> 1;                 // hi chunk
                *(uint4*)(a + r * 64 + ((kc ^ vx) << 4)) = make_uint4(h0, h1, ph0, ph1);
            } else {
                const int kc = 2 + (aq >> 1);           // lo chunk
                *(uint4*)(a + r * 64 + ((kc ^ vx) << 4)) = make_uint4(pl0, pl1, l0, l1);
            }
        }
        uint8_t* bsm = Bs[buf];
#pragma unroll
        for (int i = 0; i < 2; i++) {
            int idx = tid + i * 128;
            if (idx < 160) {
                int rb = idx >> 1, hb = idx & 1;
                *(uint4*)(bsm + rb * BSTRIDE + hb * 16) = bst[i];
            }
        }
    };

    auto COMPUTE = [&](int buf) {
        const uint8_t* a   = As[buf];
        const uint8_t* bsm = Bs[buf];
        uint32_t bf[10][2];
#pragma unroll
        for (int ni = 0; ni < 10; ni++) {
            const int nr = ni * 8 + g;
            bf[ni][0] = *(const uint32_t*)(bsm + nr * BSTRIDE + tg * 4);
            bf[ni][1] = *(const uint32_t*)(bsm + nr * BSTRIDE + 16 + tg * 4);
        }
#pragma unroll
        for (int p = 0; p < 2; p++) {           // hi plane, lo plane
#pragma unroll
            for (int mi = 0; mi < 2; mi++) {
                const int r0 = wid * 32 + mi * 16 + g;
                const int r1 = r0 + 8;
                const int v0 = (r0 >> 1) & 3;
                const int v1 = (r1 >> 1) & 3;
                uint32_t a0 = *(const uint32_t*)(a + r0 * 64 + (((2 * p)     ^ v0) << 4) + tg * 4);
                uint32_t a1 = *(const uint32_t*)(a + r1 * 64 + (((2 * p)     ^ v1) << 4) + tg * 4);
                uint32_t a2 = *(const uint32_t*)(a + r0 * 64 + (((2 * p + 1) ^ v0) << 4) + tg * 4);
                uint32_t a3 = *(const uint32_t*)(a + r1 * 64 + (((2 * p + 1) ^ v1) << 4) + tg * 4);
#pragma unroll
                for (int ni = 0; ni < 10; ni++)
                    mma16816(acc[mi][ni], a0, a1, a2, a3, bf[ni][0], bf[ni][1]);
            }
        }
    };

    // ---- pipeline ----
    LOADG(0);
    STORE(0);
    __syncthreads();
    for (int kt = 0; kt < NSTAGE; kt++) {
        const int buf = kt & 1;
        if (kt < NSTAGE - 1) LOADG((kt + 1) * 16);
        COMPUTE(buf);
        if (kt < NSTAGE - 1) STORE(buf ^ 1);
        __syncthreads();
    }

    // ---- epilogue: +b1, ternarize, int8 store ----
#pragma unroll
    for (int mi = 0; mi < 2; mi++) {
        const int r0 = m0 + wid * 32 + mi * 16 + g;
#pragma unroll
        for (int ni = 0; ni < 10; ni++) {
            const int col = ni * 8 + tg * 2;
            const float bv0 = b1s[col], bv1 = b1s[col + 1];
            char2 c01, c23;
            c01.x = (signed char)tern_i(acc[mi][ni][0] + bv0);
            c01.y = (signed char)tern_i(acc[mi][ni][1] + bv1);
            c23.x = (signed char)tern_i(acc[mi][ni][2] + bv0);
            c23.y = (signed char)tern_i(acc[mi][ni][3] + bv1);
            *(char2*)(g_h + (size_t)r0 * DH + n0 + col)       = c01;
            *(char2*)(g_h + (size_t)(r0 + 8) * DH + n0 + col) = c23;
        }
    }
}

// ============================================================================
// Head: logits = g_h @ tern(w2)^T + b2 ; log_softmax. 2 threads per row.
// ============================================================================
__global__ __launch_bounds__(256)
void head_kernel(const float* __restrict__ w2,
                 const float* __restrict__ b2,
                 float* __restrict__ out) {
    __shared__ int   q2p[DOUT][DH / 4];
    __shared__ float b2s[DOUT];

    const int tid = threadIdx.x;
    for (int i = tid; i < DOUT * (DH / 4); i += 256) {
        const int o = i / (DH / 4);
        const int w = i % (DH / 4);
        int word = 0;
#pragma unroll
        for (int j = 0; j < 4; j++) {
            int t = tern_i(w2[o * DH + w * 4 + j]);
            word |= (t & 0xFF) << (8 * j);
        }
        q2p[o][w] = word;
    }
    if (tid < DOUT) b2s[tid] = b2[tid];
    __syncthreads();

    const int gidx   = blockIdx.x * 256 + tid;
    const size_t row = (size_t)(gidx >> 1);
    const int half   = gidx & 1;
    const uint4* hp  = (const uint4*)(g_h + row * DH) + half * 10;

    int acc[DOUT];
#pragma unroll
    for (int o = 0; o < DOUT; o++) acc[o] = 0;

#pragma unroll
    for (int c = 0; c < 10; c++) {          // 10 x uint4 = 160 int8 per thread
        uint4 v = hp[c];
        const int w = half * 40 + c * 4;
#pragma unroll
        for (int o = 0; o < DOUT; o++) {
            acc[o] = __dp4a((int)v.x, q2p[o][w + 0], acc[o]);
            acc[o] = __dp4a((int)v.y, q2p[o][w + 1], acc[o]);
            acc[o] = __dp4a((int)v.z, q2p[o][w + 2], acc[o]);
            acc[o] = __dp4a((int)v.w, q2p[o][w + 3], acc[o]);
        }
    }
#pragma unroll
    for (int o = 0; o < DOUT; o++)
        acc[o] += __shfl_xor_sync(0xFFFFFFFFu, acc[o], 1);

    if (half == 0) {
        float lg[DOUT];
        float m = -1e30f;
#pragma unroll
        for (int o = 0; o < DOUT; o++) {
            lg[o] = (float)acc[o] + b2s[o];
            m = fmaxf(m, lg[o]);
        }
        float s = 0.0f;
#pragma unroll
        for (int o = 0; o < DOUT; o++) s += expf(lg[o] - m);
        const float lse = m + logf(s);
        float* op = out + row * DOUT;
#pragma unroll
        for (int o = 0; o < DOUT; o++) op[o] = lg[o] - lse;
    }
}

// ============================================================================
extern "C" void kernel_launch(void* const* d_in, const int* in_sizes, int n_in,
                              void* d_out, int out_size) {
    const float* x  = (const float*)d_in[0];
    const float* w1 = (const float*)d_in[1];
    const float* b1 = (const float*)d_in[2];
    const float* w2 = (const float*)d_in[3];
    const float* b2 = (const float*)d_in[4];
    float* out = (float*)d_out;

    prep_w1<<<(DH * DIN / 2 + 255) / 256, 256>>>(w1);
    gemm1_hmma<<<dim3(DH / BN, BATCH / BM), 128>>>(x, b1);
    head_kernel<<<BATCH * 2 / 256, 256>>>(w2, b2, out);
}

// round 4
// speedup vs baseline: 2.4991x; 1.2817x over previous
#include <cuda_runtime.h>
#include <cuda_fp16.h>
#include <cstdint>

#define BATCH 65536
#define DIN   784
#define DH    320
#define DOUT  10
#define THRESH 0.001f

// GEMM1 tiling
#define BM 128
#define BN 160
#define KC 32              // fp32 K per stage
#define NST 25             // 24 full stages + 1 of K=16
#define ABUF 16384         // 128 rows x 128B (8 chunks of 16B: 4 hi + 4 lo)
#define BBUF 12800         // 160 rows x 80B (4 chunks of 16B + 16B pad)
#define BSTR 80
#define SMEM_TOTAL (2*ABUF + 2*BBUF + BN*4)   // 59648... 32768+25600+640 = 59008

__device__ __align__(16) int8_t g_h[(size_t)BATCH * DH];
__device__ __align__(16) __half g_w1h[(size_t)DH * DIN];

__device__ __forceinline__ int tern_i(float v) {
    return v > THRESH ? 1 : (v < -THRESH ? -1 : 0);
}
__device__ __forceinline__ uint32_t h2u(__half2 h) {
    return *reinterpret_cast<uint32_t*>(&h);
}
__device__ __forceinline__ uint32_t smem_u32(const void* p) {
    uint32_t a;
    asm("{ .reg .u64 t; cvta.to.shared.u64 t, %1; cvt.u32.u64 %0, t; }" : "=r"(a) : "l"(p));
    return a;
}
__device__ __forceinline__ void mma16816(float* c, uint32_t a0, uint32_t a1,
                                         uint32_t a2, uint32_t a3,
                                         uint32_t b0, uint32_t b1) {
    asm volatile(
        "mma.sync.aligned.m16n8k16.row.col.f32.f16.f16.f32 "
        "{%0,%1,%2,%3}, {%4,%5,%6,%7}, {%8,%9}, {%0,%1,%2,%3};"
        : "+f"(c[0]), "+f"(c[1]), "+f"(c[2]), "+f"(c[3])
        : "r"(a0), "r"(a1), "r"(a2), "r"(a3), "r"(b0), "r"(b1));
}
__device__ __forceinline__ void ldsm4(uint32_t& r0, uint32_t& r1,
                                      uint32_t& r2, uint32_t& r3, uint32_t a) {
    asm volatile("ldmatrix.sync.aligned.m8n8.x4.shared.b16 {%0,%1,%2,%3}, [%4];"
                 : "=r"(r0), "=r"(r1), "=r"(r2), "=r"(r3) : "r"(a));
}
__device__ __forceinline__ void sts128(uint32_t a, uint32_t x, uint32_t y,
                                       uint32_t z, uint32_t w) {
    asm volatile("st.shared.v4.b32 [%0], {%1,%2,%3,%4};" :: "r"(a), "r"(x), "r"(y), "r"(z), "r"(w));
}
__device__ __forceinline__ void cpasync16(uint32_t s, const void* g, int pred) {
    asm volatile(
        "{ .reg .pred p; setp.ne.b32 p, %2, 0;\n\t"
        "@p cp.async.cg.shared.global [%0], [%1], 16; }\n"
        :: "r"(s), "l"(g), "r"(pred));
}
#define CP_COMMIT() asm volatile("cp.async.commit_group;" ::: "memory")
#define CP_WAIT0()  asm volatile("cp.async.wait_group 0;" ::: "memory")

// ============================================================================
// prep: ternarize w1 -> fp16 (exact)
// ============================================================================
__global__ void prep_w1(const float* __restrict__ w1) {
    int i = blockIdx.x * 256 + threadIdx.x;
    if (i >= DH * DIN / 2) return;
    float a = w1[2 * i], b = w1[2 * i + 1];
    reinterpret_cast<__half2*>(g_w1h)[i] =
        __floats2half2_rn((float)tern_i(a), (float)tern_i(b));
}

// ============================================================================
// GEMM1: h = tern( x @ tern(w1)^T + b1 ).  HMMA, 2-plane exact fp16 split.
// CTA 128x160, 8 warps (4M x 2N), K=32/stage, ldmatrix frags, cp.async B.
// A smem: row r, chunk c (0..7: 4 hi + 4 lo 16B chunks) at r*128 + ((c^(r&7))<<4)
// B smem: row n, chunk c (0..3) at n*80 + c*16
// ============================================================================
__global__ __launch_bounds__(256, 1)
void gemm1_hmma(const float* __restrict__ x, const float* __restrict__ b1) {
    extern __shared__ __align__(16) uint8_t sm[];
    const uint32_t base = smem_u32(sm);
    float* b1s = (float*)(sm + 2 * ABUF + 2 * BBUF);

    const int tid  = threadIdx.x;
    const int wid  = tid >> 5;
    const int lane = tid & 31;
    const int wm   = wid >> 1;       // M band 0..3
    const int wn   = wid & 1;        // N band 0..1
    const int g    = lane >> 2;
    const int tg   = lane & 3;
    const int m0   = blockIdx.y * BM;
    const int n0   = blockIdx.x * BN;

    if (tid < BN) b1s[tid] = b1[n0 + tid];

    float acc[2][10][4];
#pragma unroll
    for (int mi = 0; mi < 2; mi++)
#pragma unroll
        for (int ni = 0; ni < 10; ni++)
#pragma unroll
            for (int e = 0; e < 4; e++) acc[mi][ni][e] = 0.0f;

    // ---- frag address precompute ----
    const int cxor = lane & 7;
    const int chi  = lane >> 4;                      // A chunk selector bit
    uint32_t arow[2];
#pragma unroll
    for (int mi = 0; mi < 2; mi++)
        arow[mi] = (uint32_t)((wm * 32 + mi * 16 + (lane & 15)) * 128);
    uint32_t bno[5];
#pragma unroll
    for (int j = 0; j < 5; j++)
        bno[j] = (uint32_t)((wn * 80 + j * 16 + (lane & 7) + ((lane >> 4) & 1) * 8) * BSTR
                            + ((lane >> 3) & 1) * 16);

    // ---- A gmem staging: one thread = one (row, k-half) ----
    const int ar = tid >> 1;         // 0..127
    const int hh = tid & 1;          // k 0-15 or 16-31
    const float* xrow = x + (size_t)(m0 + ar) * DIN + hh * 16;
    float4 v0, v1, v2, v3;

    auto LOADA = [&](int k0, int full) {
        if (hh == 0 || full) {
            const float4* p = (const float4*)(xrow + k0);
            v0 = p[0]; v1 = p[1]; v2 = p[2]; v3 = p[3];
        }
    };
    auto ISSUEB = [&](int k0, int buf, int full) {
        const uint32_t bb = base + 2 * ABUF + (uint32_t)buf * BBUF;
#pragma unroll
        for (int i = 0; i < 3; i++) {
            int idx = tid + i * 256;
            int ok  = (idx < 640);
            int row = idx >> 2, ch = idx & 3;
            if (!full) ok = ok && (ch < 2);
            cpasync16(bb + (uint32_t)(row * BSTR + ch * 16),
                      g_w1h + (size_t)(n0 + (ok ? row : 0)) * DIN + k0 + (ok ? ch : 0) * 8,
                      ok);
        }
        CP_COMMIT();
    };
    auto STOREA = [&](int buf, int full) {
        if (hh == 0 || full) {
            const uint32_t ab = base + (uint32_t)buf * ABUF + (uint32_t)(ar * 128);
            const int sw = ar & 7;
            __half2 h0 = __floats2half2_rn(v0.x, v0.y), h1 = __floats2half2_rn(v0.z, v0.w);
            __half2 h2 = __floats2half2_rn(v1.x, v1.y), h3 = __floats2half2_rn(v1.z, v1.w);
            __half2 h4 = __floats2half2_rn(v2.x, v2.y), h5 = __floats2half2_rn(v2.z, v2.w);
            __half2 h6 = __floats2half2_rn(v3.x, v3.y), h7 = __floats2half2_rn(v3.z, v3.w);
            float2 f0 = __half22float2(h0), f1 = __half22float2(h1);
            float2 f2 = __half22float2(h2), f3 = __half22float2(h3);
            float2 f4 = __half22float2(h4), f5 = __half22float2(h5);
            float2 f6 = __half22float2(h6), f7 = __half22float2(h7);
            uint32_t l0 = h2u(__floats2half2_rn(v0.x - f0.x, v0.y - f0.y));
            uint32_t l1 = h2u(__floats2half2_rn(v0.z - f1.x, v0.w - f1.y));
            uint32_t l2 = h2u(__floats2half2_rn(v1.x - f2.x, v1.y - f2.y));
            uint32_t l3 = h2u(__floats2half2_rn(v1.z - f3.x, v1.w - f3.y));
            uint32_t l4 = h2u(__floats2half2_rn(v2.x - f4.x, v2.y - f4.y));
            uint32_t l5 = h2u(__floats2half2_rn(v2.z - f5.x, v2.w - f5.y));
            uint32_t l6 = h2u(__floats2half2_rn(v3.x - f6.x, v3.y - f6.y));
            uint32_t l7 = h2u(__floats2half2_rn(v3.z - f7.x, v3.w - f7.y));
            const int c0 = hh * 2, c1 = hh * 2 + 1;
            sts128(ab + (uint32_t)(((c0)     ^ sw) << 4), h2u(h0), h2u(h1), h2u(h2), h2u(h3));
            sts128(ab + (uint32_t)(((c1)     ^ sw) << 4), h2u(h4), h2u(h5), h2u(h6), h2u(h7));
            sts128(ab + (uint32_t)(((c0 + 4) ^ sw) << 4), l0, l1, l2, l3);
            sts128(ab + (uint32_t)(((c1 + 4) ^ sw) << 4), l4, l5, l6, l7);
        }
    };

    auto KSTEP = [&](int buf, int ks) {
        const uint32_t ab = base + (uint32_t)buf * ABUF;
        const uint32_t bb = base + 2 * ABUF + (uint32_t)buf * BBUF;
        uint32_t bf[20];
#pragma unroll
        for (int j = 0; j < 5; j++)
            ldsm4(bf[4 * j], bf[4 * j + 1], bf[4 * j + 2], bf[4 * j + 3],
                  bb + bno[j] + (uint32_t)(ks * 32));
#pragma unroll
        for (int p = 0; p < 2; p++) {
#pragma unroll
            for (int mi = 0; mi < 2; mi++) {
                uint32_t a0, a1, a2, a3;
                const uint32_t co =
                    (uint32_t)((((p * 4 + ks * 2 + chi) ^ cxor)) << 4);
                ldsm4(a0, a1, a2, a3, ab + arow[mi] + co);
#pragma unroll
                for (int ni = 0; ni < 10; ni++)
                    mma16816(acc[mi][ni], a0, a1, a2, a3, bf[2 * ni], bf[2 * ni + 1]);
            }
        }
    };

    // ---- pipeline ----
    ISSUEB(0, 0, 1);
    LOADA(0, 1);
    STOREA(0, 1);
    CP_WAIT0();
    __syncthreads();

    for (int kt = 0; kt < NST - 1; kt++) {
        const int buf  = kt & 1;
        const int full = (kt + 1 < NST - 1) ? 1 : 0;
        ISSUEB((kt + 1) * KC, buf ^ 1, full);
        LOADA((kt + 1) * KC - hh * 16 * 0 + 0, full);   // k0 = (kt+1)*KC (xrow already offset by hh*16)
        // NOTE: xrow includes hh*16; LOADA adds stage k0 only.
        KSTEP(buf, 0);
        KSTEP(buf, 1);
        STOREA(buf ^ 1, full);
        CP_WAIT0();
        __syncthreads();
    }
    // final stage (K=16), buf = (NST-1)&1 = 0
    KSTEP(0, 0);

    // ---- epilogue: +b1, ternarize, int8 store ----
#pragma unroll
    for (int mi = 0; mi < 2; mi++) {
        const int r0 = m0 + wm * 32 + mi * 16 + g;
#pragma unroll
        for (int ni = 0; ni < 10; ni++) {
            const int col = wn * 80 + ni * 8 + tg * 2;
            const float bv0 = b1s[col], bv1 = b1s[col + 1];
            char2 c01, c23;
            c01.x = (signed char)tern_i(acc[mi][ni][0] + bv0);
            c01.y = (signed char)tern_i(acc[mi][ni][1] + bv1);
            c23.x = (signed char)tern_i(acc[mi][ni][2] + bv0);
            c23.y = (signed char)tern_i(acc[mi][ni][3] + bv1);
            *(char2*)(g_h + (size_t)r0 * DH + n0 + col)       = c01;
            *(char2*)(g_h + (size_t)(r0 + 8) * DH + n0 + col) = c23;
        }
    }
}

// ============================================================================
// Head: logits = g_h @ tern(w2)^T + b2 ; log_softmax. 4 threads per row.
// ============================================================================
__global__ __launch_bounds__(256)
void head_kernel(const float* __restrict__ w2,
                 const float* __restrict__ b2,
                 float* __restrict__ out) {
    __shared__ int   q2p[DOUT][DH / 4];
    __shared__ float b2s[DOUT];

    const int tid = threadIdx.x;
    for (int i = tid; i < DOUT * (DH / 4); i += 256) {
        const int o = i / (DH / 4);
        const int w = i % (DH / 4);
        int word = 0;
#pragma unroll
        for (int j = 0; j < 4; j++) {
            int t = tern_i(w2[o * DH + w * 4 + j]);
            word |= (t & 0xFF) << (8 * j);
        }
        q2p[o][w] = word;
    }
    if (tid < DOUT) b2s[tid] = b2[tid];
    __syncthreads();

    const int gidx   = blockIdx.x * 256 + tid;
    const size_t row = (size_t)(gidx >> 2);
    const int q      = gidx & 3;
    const uint4* hp  = (const uint4*)(g_h + row * DH) + q * 5;

    int acc[DOUT];
#pragma unroll
    for (int o = 0; o < DOUT; o++) acc[o] = 0;

#pragma unroll
    for (int c = 0; c < 5; c++) {            // 5 x uint4 = 80 int8 per thread
        uint4 v = hp[c];
        const int w = q * 20 + c * 4;
#pragma unroll
        for (int o = 0; o < DOUT; o++) {
            acc[o] = __dp4a((int)v.x, q2p[o][w + 0], acc[o]);
            acc[o] = __dp4a((int)v.y, q2p[o][w + 1], acc[o]);
            acc[o] = __dp4a((int)v.z, q2p[o][w + 2], acc[o]);
            acc[o] = __dp4a((int)v.w, q2p[o][w + 3], acc[o]);
        }
    }
#pragma unroll
    for (int o = 0; o < DOUT; o++) {
        acc[o] += __shfl_xor_sync(0xFFFFFFFFu, acc[o], 1);
        acc[o] += __shfl_xor_sync(0xFFFFFFFFu, acc[o], 2);
    }

    if (q == 0) {
        float lg[DOUT];
        float m = -1e30f;
#pragma unroll
        for (int o = 0; o < DOUT; o++) {
            lg[o] = (float)acc[o] + b2s[o];
            m = fmaxf(m, lg[o]);
        }
        float s = 0.0f;
#pragma unroll
        for (int o = 0; o < DOUT; o++) s += expf(lg[o] - m);
        const float lse = m + logf(s);
        float* op = out + row * DOUT;
#pragma unroll
        for (int o = 0; o < DOUT; o++) op[o] = lg[o] - lse;
    }
}

// ============================================================================
extern "C" void kernel_launch(void* const* d_in, const int* in_sizes, int n_in,
                              void* d_out, int out_size) {
    const float* x  = (const float*)d_in[0];
    const float* w1 = (const float*)d_in[1];
    const float* b1 = (const float*)d_in[2];
    const float* w2 = (const float*)d_in[3];
    const float* b2 = (const float*)d_in[4];
    float* out = (float*)d_out;

    static int configured = 0;
    if (!configured) {
        cudaFuncSetAttribute(gemm1_hmma,
                             cudaFuncAttributeMaxDynamicSharedMemorySize, SMEM_TOTAL);
        configured = 1;
    }

    prep_w1<<<(DH * DIN / 2 + 255) / 256, 256>>>(w1);
    gemm1_hmma<<<dim3(DH / BN, BATCH / BM), 256, SMEM_TOTAL>>>(x, b1);
    head_kernel<<<BATCH * 4 / 256, 256>>>(w2, b2, out);
}

// round 5
// speedup vs baseline: 2.7841x; 1.1141x over previous
#include <cuda_runtime.h>
#include <cuda_fp16.h>
#include <cstdint>

#define BATCH 65536
#define DIN   784
#define DH    320
#define DOUT  10
#define THRESH 0.001f

// GEMM1 tiling
#define BM 128
#define BN 160
#define KC 32              // fp32 K per stage
#define NST 25             // 24 full stages + 1 of K=16
#define ABUF 16384         // 128 rows x 128B (8 chunks of 16B: 4 hi + 4 lo)
#define BBUF 12800         // 160 rows x 80B (4 chunks of 16B + 16B pad)
#define BSTR 80
#define SMEM_TOTAL (2*ABUF + 2*BBUF + BN*4)   // 59008

__device__ __align__(16) int8_t g_h[(size_t)BATCH * DH];
__device__ __align__(16) __half g_w1h[(size_t)DH * DIN];

__device__ __forceinline__ int tern_i(float v) {
    return v > THRESH ? 1 : (v < -THRESH ? -1 : 0);
}
__device__ __forceinline__ uint32_t h2u(__half2 h) {
    return *reinterpret_cast<uint32_t*>(&h);
}
__device__ __forceinline__ uint32_t smem_u32(const void* p) {
    uint32_t a;
    asm("{ .reg .u64 t; cvta.to.shared.u64 t, %1; cvt.u32.u64 %0, t; }" : "=r"(a) : "l"(p));
    return a;
}
__device__ __forceinline__ void mma16816(float* c, uint32_t a0, uint32_t a1,
                                         uint32_t a2, uint32_t a3,
                                         uint32_t b0, uint32_t b1) {
    asm volatile(
        "mma.sync.aligned.m16n8k16.row.col.f32.f16.f16.f32 "
        "{%0,%1,%2,%3}, {%4,%5,%6,%7}, {%8,%9}, {%0,%1,%2,%3};"
        : "+f"(c[0]), "+f"(c[1]), "+f"(c[2]), "+f"(c[3])
        : "r"(a0), "r"(a1), "r"(a2), "r"(a3), "r"(b0), "r"(b1));
}
__device__ __forceinline__ void ldsm4(uint32_t& r0, uint32_t& r1,
                                      uint32_t& r2, uint32_t& r3, uint32_t a) {
    asm volatile("ldmatrix.sync.aligned.m8n8.x4.shared.b16 {%0,%1,%2,%3}, [%4];"
                 : "=r"(r0), "=r"(r1), "=r"(r2), "=r"(r3) : "r"(a));
}
__device__ __forceinline__ void ldsm2(uint32_t& r0, uint32_t& r1, uint32_t a) {
    asm volatile("ldmatrix.sync.aligned.m8n8.x2.shared.b16 {%0,%1}, [%2];"
                 : "=r"(r0), "=r"(r1) : "r"(a));
}
__device__ __forceinline__ void sts128(uint32_t a, uint32_t x, uint32_t y,
                                       uint32_t z, uint32_t w) {
    asm volatile("st.shared.v4.b32 [%0], {%1,%2,%3,%4};" :: "r"(a), "r"(x), "r"(y), "r"(z), "r"(w));
}
__device__ __forceinline__ void cpasync16(uint32_t s, const void* g, int pred) {
    asm volatile(
        "{ .reg .pred p; setp.ne.b32 p, %2, 0;\n\t"
        "@p cp.async.cg.shared.global [%0], [%1], 16; }\n"
        :: "r"(s), "l"(g), "r"(pred));
}
#define CP_COMMIT() asm volatile("cp.async.commit_group;" ::: "memory")
#define CP_WAIT0()  asm volatile("cp.async.wait_group 0;" ::: "memory")

// ============================================================================
// prep: ternarize w1 -> fp16 (exact)
// ============================================================================
__global__ void prep_w1(const float* __restrict__ w1) {
    int i = blockIdx.x * 256 + threadIdx.x;
    if (i >= DH * DIN / 2) return;
    float a = w1[2 * i], b = w1[2 * i + 1];
    reinterpret_cast<__half2*>(g_w1h)[i] =
        __floats2half2_rn((float)tern_i(a), (float)tern_i(b));
}

// ============================================================================
// GEMM1: h = tern( x @ tern(w1)^T + b1 ).  HMMA, 2-plane exact fp16 split.
// 512 threads / 16 warps (4M x 4N), warp tile 32x40. K=32/stage.
// A smem: row r, chunk c (0..7: 4 hi + 4 lo 16B chunks) at r*128 + ((c^(r&7))<<4)
// B smem: row n, chunk c (0..3) at n*80 + c*16
// ============================================================================
__global__ __launch_bounds__(512, 1)
void gemm1_hmma(const float* __restrict__ x, const float* __restrict__ b1) {
    extern __shared__ __align__(16) uint8_t sm[];
    const uint32_t base = smem_u32(sm);
    float* b1s = (float*)(sm + 2 * ABUF + 2 * BBUF);

    const int tid  = threadIdx.x;
    const int lane = tid & 31;
    const int wid  = tid >> 5;
    const int wm   = wid >> 2;       // M band 0..3 (32 rows)
    const int wn   = wid & 3;        // N band 0..3 (40 cols)
    const int g    = lane >> 2;
    const int tg   = lane & 3;
    const int m0   = blockIdx.y * BM;
    const int n0   = blockIdx.x * BN;

    if (tid < BN) b1s[tid] = b1[n0 + tid];

    float acc[2][5][4];
#pragma unroll
    for (int mi = 0; mi < 2; mi++)
#pragma unroll
        for (int ni = 0; ni < 5; ni++)
#pragma unroll
            for (int e = 0; e < 4; e++) acc[mi][ni][e] = 0.0f;

    // ---- frag address precompute ----
    const int cxor = lane & 7;
    const int chi  = lane >> 4;                      // A k-half chunk selector
    uint32_t arow[2];
#pragma unroll
    for (int mi = 0; mi < 2; mi++)
        arow[mi] = (uint32_t)((wm * 32 + mi * 16 + (lane & 15)) * 128);
    // B: two ldsm4 (n 0..31 of band) + one ldsm2 (n 32..39)
    uint32_t bno[2];
#pragma unroll
    for (int j = 0; j < 2; j++)
        bno[j] = (uint32_t)((wn * 40 + j * 16 + (lane & 7) + ((lane >> 4) & 1) * 8) * BSTR
                            + ((lane >> 3) & 1) * 16);
    const uint32_t bno2 = (uint32_t)((wn * 40 + 32 + (lane & 7)) * BSTR
                                     + ((lane >> 3) & 1) * 16);

    // ---- A gmem staging: one thread = one (row, 8-fp32 k-group) ----
    const int ar = tid >> 2;         // 0..127
    const int aq = tid & 3;          // k group: k = aq*8 .. aq*8+7
    const float* xrow = x + (size_t)(m0 + ar) * DIN + aq * 8;
    float4 v0, v1;

    auto LOADA = [&](int k0, int full) {
        if (aq < 2 || full) {
            const float4* p = (const float4*)(xrow + k0);
            v0 = p[0]; v1 = p[1];
        }
    };
    auto ISSUEB = [&](int k0, int buf, int full) {
        const uint32_t bb = base + 2 * ABUF + (uint32_t)buf * BBUF;
#pragma unroll
        for (int i = 0; i < 2; i++) {
            int idx = tid + i * 512;
            int row = idx >> 2, ch = idx & 3;
            int ok  = (idx < 640) && (full || ch < 2);
            cpasync16(bb + (uint32_t)(row * BSTR + ch * 16),
                      g_w1h + (size_t)(n0 + (ok ? row : 0)) * DIN + k0 + (ok ? ch : 0) * 8,
                      ok);
        }
        CP_COMMIT();
    };
    auto STOREA = [&](int buf, int full) {
        if (aq < 2 || full) {
            const uint32_t ab = base + (uint32_t)buf * ABUF + (uint32_t)(ar * 128);
            const int sw = ar & 7;
            __half2 h0 = __floats2half2_rn(v0.x, v0.y), h1 = __floats2half2_rn(v0.z, v0.w);
            __half2 h2 = __floats2half2_rn(v1.x, v1.y), h3 = __floats2half2_rn(v1.z, v1.w);
            float2 f0 = __half22float2(h0), f1 = __half22float2(h1);
            float2 f2 = __half22float2(h2), f3 = __half22float2(h3);
            uint32_t l0 = h2u(__floats2half2_rn(v0.x - f0.x, v0.y - f0.y));
            uint32_t l1 = h2u(__floats2half2_rn(v0.z - f1.x, v0.w - f1.y));
            uint32_t l2 = h2u(__floats2half2_rn(v1.x - f2.x, v1.y - f2.y));
            uint32_t l3 = h2u(__floats2half2_rn(v1.z - f3.x, v1.w - f3.y));
            sts128(ab + (uint32_t)((aq       ^ sw) << 4), h2u(h0), h2u(h1), h2u(h2), h2u(h3));
            sts128(ab + (uint32_t)(((aq + 4) ^ sw) << 4), l0, l1, l2, l3);
        }
    };

    auto KSTEP = [&](int buf, int ks) {
        const uint32_t ab = base + (uint32_t)buf * ABUF;
        const uint32_t bb = base + 2 * ABUF + (uint32_t)buf * BBUF;
        uint32_t bf[10];
#pragma unroll
        for (int j = 0; j < 2; j++)
            ldsm4(bf[4 * j], bf[4 * j + 1], bf[4 * j + 2], bf[4 * j + 3],
                  bb + bno[j] + (uint32_t)(ks * 32));
        ldsm2(bf[8], bf[9], bb + bno2 + (uint32_t)(ks * 32));
#pragma unroll
        for (int p = 0; p < 2; p++) {
#pragma unroll
            for (int mi = 0; mi < 2; mi++) {
                uint32_t a0, a1, a2, a3;
                const uint32_t co =
                    (uint32_t)((((p * 4 + ks * 2 + chi) ^ cxor)) << 4);
                ldsm4(a0, a1, a2, a3, ab + arow[mi] + co);
#pragma unroll
                for (int ni = 0; ni < 5; ni++)
                    mma16816(acc[mi][ni], a0, a1, a2, a3, bf[2 * ni], bf[2 * ni + 1]);
            }
        }
    };

    // ---- pipeline ----
    ISSUEB(0, 0, 1);
    LOADA(0, 1);
    STOREA(0, 1);
    CP_WAIT0();
    __syncthreads();

    for (int kt = 0; kt < NST - 1; kt++) {
        const int buf  = kt & 1;
        const int full = (kt + 1 < NST - 1) ? 1 : 0;
        ISSUEB((kt + 1) * KC, buf ^ 1, full);
        LOADA((kt + 1) * KC, full);
        KSTEP(buf, 0);
        KSTEP(buf, 1);
        STOREA(buf ^ 1, full);
        CP_WAIT0();
        __syncthreads();
    }
    // final stage (K=16), buf = (NST-1)&1 = 0
    KSTEP(0, 0);

    // ---- epilogue: +b1, ternarize, int8 store ----
#pragma unroll
    for (int mi = 0; mi < 2; mi++) {
        const int r0 = m0 + wm * 32 + mi * 16 + g;
#pragma unroll
        for (int ni = 0; ni < 5; ni++) {
            const int col = wn * 40 + ni * 8 + tg * 2;
            const float bv0 = b1s[col], bv1 = b1s[col + 1];
            char2 c01, c23;
            c01.x = (signed char)tern_i(acc[mi][ni][0] + bv0);
            c01.y = (signed char)tern_i(acc[mi][ni][1] + bv1);
            c23.x = (signed char)tern_i(acc[mi][ni][2] + bv0);
            c23.y = (signed char)tern_i(acc[mi][ni][3] + bv1);
            *(char2*)(g_h + (size_t)r0 * DH + n0 + col)       = c01;
            *(char2*)(g_h + (size_t)(r0 + 8) * DH + n0 + col) = c23;
        }
    }
}

// ============================================================================
// Head: logits = g_h @ tern(w2)^T + b2 ; log_softmax. 4 threads per row.
// ============================================================================
__global__ __launch_bounds__(256)
void head_kernel(const float* __restrict__ w2,
                 const float* __restrict__ b2,
                 float* __restrict__ out) {
    __shared__ int   q2p[DOUT][DH / 4];
    __shared__ float b2s[DOUT];

    const int tid = threadIdx.x;
    for (int i = tid; i < DOUT * (DH / 4); i += 256) {
        const int o = i / (DH / 4);
        const int w = i % (DH / 4);
        int word = 0;
#pragma unroll
        for (int j = 0; j < 4; j++) {
            int t = tern_i(w2[o * DH + w * 4 + j]);
            word |= (t & 0xFF) << (8 * j);
        }
        q2p[o][w] = word;
    }
    if (tid < DOUT) b2s[tid] = b2[tid];
    __syncthreads();

    const int gidx   = blockIdx.x * 256 + tid;
    const size_t row = (size_t)(gidx >> 2);
    const int q      = gidx & 3;
    const uint4* hp  = (const uint4*)(g_h + row * DH) + q * 5;

    int acc[DOUT];
#pragma unroll
    for (int o = 0; o < DOUT; o++) acc[o] = 0;

#pragma unroll
    for (int c = 0; c < 5; c++) {
        uint4 v = hp[c];
        const int w = q * 20 + c * 4;
#pragma unroll
        for (int o = 0; o < DOUT; o++) {
            acc[o] = __dp4a((int)v.x, q2p[o][w + 0], acc[o]);
            acc[o] = __dp4a((int)v.y, q2p[o][w + 1], acc[o]);
            acc[o] = __dp4a((int)v.z, q2p[o][w + 2], acc[o]);
            acc[o] = __dp4a((int)v.w, q2p[o][w + 3], acc[o]);
        }
    }
#pragma unroll
    for (int o = 0; o < DOUT; o++) {
        acc[o] += __shfl_xor_sync(0xFFFFFFFFu, acc[o], 1);
        acc[o] += __shfl_xor_sync(0xFFFFFFFFu, acc[o], 2);
    }

    if (q == 0) {
        float lg[DOUT];
        float m = -1e30f;
#pragma unroll
        for (int o = 0; o < DOUT; o++) {
            lg[o] = (float)acc[o] + b2s[o];
            m = fmaxf(m, lg[o]);
        }
        float s = 0.0f;
#pragma unroll
        for (int o = 0; o < DOUT; o++) s += expf(lg[o] - m);
        const float lse = m + logf(s);
        float* op = out + row * DOUT;
#pragma unroll
        for (int o = 0; o < DOUT; o++) op[o] = lg[o] - lse;
    }
}

// ============================================================================
extern "C" void kernel_launch(void* const* d_in, const int* in_sizes, int n_in,
                              void* d_out, int out_size) {
    const float* x  = (const float*)d_in[0];
    const float* w1 = (const float*)d_in[1];
    const float* b1 = (const float*)d_in[2];
    const float* w2 = (const float*)d_in[3];
    const float* b2 = (const float*)d_in[4];
    float* out = (float*)d_out;

    static int configured = 0;
    if (!configured) {
        cudaFuncSetAttribute(gemm1_hmma,
                             cudaFuncAttributeMaxDynamicSharedMemorySize, SMEM_TOTAL);
        configured = 1;
    }

    prep_w1<<<(DH * DIN / 2 + 255) / 256, 256>>>(w1);
    gemm1_hmma<<<dim3(DH / BN, BATCH / BM), 512, SMEM_TOTAL>>>(x, b1);
    head_kernel<<<BATCH * 4 / 256, 256>>>(w2, b2, out);
}